// round 2
// baseline (speedup 1.0000x reference)
#include <cuda_runtime.h>
#include <cuda_bf16.h>
#include <cstdint>
#include <cstddef>

#define DIN  4096
#define DOUT 4096
#define RNK  8
#define MTOT 8192            // 4*2048 rows of x

// ------------------------- scratch (__device__ globals) -------------------------
__device__ float g_un[RNK * DIN];          // normalized Householder vectors, [r][DIN]
__device__ float g_T[RNK * RNK];           // compact-WY T (8x8)
__device__ float g_P[DOUT * RNK];          // P = (W U) T, [DOUT][8]
__device__ __nv_bfloat16 g_wh[(size_t)DOUT * DIN];
__device__ __nv_bfloat16 g_wl[(size_t)DOUT * DIN];
__device__ __nv_bfloat16 g_xh[(size_t)MTOT * DIN];
__device__ __nv_bfloat16 g_xl[(size_t)MTOT * DIN];

// ------------------------- PTX helpers (family-safe: sm_80-era) -------------------------
__device__ __forceinline__ uint32_t smem_u32(const void* p) {
    uint32_t a;
    asm("{ .reg .u64 t; cvta.to.shared.u64 t, %1; cvt.u32.u64 %0, t; }" : "=r"(a) : "l"(p));
    return a;
}

__device__ __forceinline__ void cp_async16(uint32_t saddr, const void* gptr) {
    asm volatile("cp.async.cg.shared.global [%0], [%1], 16;" :: "r"(saddr), "l"(gptr));
}
#define CP_COMMIT() asm volatile("cp.async.commit_group;" ::: "memory")
#define CP_WAIT2()  asm volatile("cp.async.wait_group 2;" ::: "memory")

#define LDMATRIX_X4(r0, r1, r2, r3, addr) \
    asm volatile("ldmatrix.sync.aligned.m8n8.x4.shared.b16 {%0,%1,%2,%3}, [%4];" \
                 : "=r"(r0), "=r"(r1), "=r"(r2), "=r"(r3) : "r"(addr))

#define MMA16816(d0, d1, d2, d3, a0, a1, a2, a3, b0, b1) \
    asm volatile("mma.sync.aligned.m16n8k16.row.col.f32.bf16.bf16.f32 " \
                 "{%0,%1,%2,%3}, {%4,%5,%6,%7}, {%8,%9}, {%0,%1,%2,%3};" \
                 : "+f"(d0), "+f"(d1), "+f"(d2), "+f"(d3) \
                 : "r"(a0), "r"(a1), "r"(a2), "r"(a3), "r"(b0), "r"(b1))

// ------------------------- K1: normalize u, Gram, build T -------------------------
__global__ void k_prep(const float* __restrict__ hra) {
    __shared__ float sR[64];
    __shared__ float sInv[8];
    int tid = threadIdx.x;
    if (tid < 64) sR[tid] = 0.f;
    __syncthreads();

    float acc[8][8];
#pragma unroll
    for (int i = 0; i < 8; i++)
#pragma unroll
        for (int j = 0; j < 8; j++) acc[i][j] = 0.f;

    for (int k = tid; k < DIN; k += 256) {
        float v[8];
#pragma unroll
        for (int i = 0; i < 8; i++) v[i] = hra[k * 8 + i];
#pragma unroll
        for (int i = 0; i < 8; i++)
#pragma unroll
            for (int j = 0; j < 8; j++) acc[i][j] += v[i] * v[j];
    }
#pragma unroll
    for (int i = 0; i < 8; i++)
#pragma unroll
        for (int j = 0; j < 8; j++) atomicAdd(&sR[i * 8 + j], acc[i][j]);
    __syncthreads();

    if (tid < 8) sInv[tid] = 1.0f / sqrtf(sR[tid * 8 + tid]);
    __syncthreads();

    for (int k = tid; k < DIN; k += 256) {
#pragma unroll
        for (int i = 0; i < 8; i++) g_un[i * DIN + k] = hra[k * 8 + i] * sInv[i];
    }

    if (tid == 0) {
        float G[8][8], T[8][8];
        for (int i = 0; i < 8; i++)
            for (int j = 0; j < 8; j++) G[i][j] = sR[i * 8 + j] * sInv[i] * sInv[j];
        for (int i = 0; i < 8; i++)
            for (int j = 0; j < 8; j++) T[i][j] = (i == j) ? 2.f : 0.f;
        for (int j = 1; j < 8; j++)
            for (int i = 0; i < j; i++) {
                float s = 0.f;
                for (int l = i; l < j; l++) s += T[i][l] * G[l][j];
                T[i][j] = -2.f * s;
            }
        for (int i = 0; i < 8; i++)
            for (int j = 0; j < 8; j++) g_T[i * 8 + j] = T[i][j];
    }
}

// ------------------------- K2: P = (W U) T  (one block per W row) -------------------------
__global__ void k_wu(const float* __restrict__ w) {
    int n = blockIdx.x;
    int tid = threadIdx.x;
    __shared__ float sAcc[8];
    if (tid < 8) sAcc[tid] = 0.f;
    __syncthreads();

    float part[8] = {0, 0, 0, 0, 0, 0, 0, 0};
    const float* wr = w + (size_t)n * DIN;
    for (int c = tid; c < DIN; c += 256) {
        float wv = wr[c];
#pragma unroll
        for (int i = 0; i < 8; i++) part[i] += wv * g_un[i * DIN + c];
    }
#pragma unroll
    for (int i = 0; i < 8; i++) {
        float v = part[i];
        v += __shfl_down_sync(0xFFFFFFFFu, v, 16);
        v += __shfl_down_sync(0xFFFFFFFFu, v, 8);
        v += __shfl_down_sync(0xFFFFFFFFu, v, 4);
        v += __shfl_down_sync(0xFFFFFFFFu, v, 2);
        v += __shfl_down_sync(0xFFFFFFFFu, v, 1);
        if ((tid & 31) == 0) atomicAdd(&sAcc[i], v);
    }
    __syncthreads();
    if (tid < 8) {
        int j = tid;
        float p = 0.f;
#pragma unroll
        for (int i = 0; i < 8; i++) p += sAcc[i] * g_T[i * 8 + j];
        g_P[n * 8 + j] = p;
    }
}

// ------------------------- split helper -------------------------
__device__ __forceinline__ void split4(float a0, float a1, float a2, float a3,
                                       uint2& hi, uint2& lo) {
    unsigned short hs[4], ls[4];
    float a[4] = {a0, a1, a2, a3};
#pragma unroll
    for (int i = 0; i < 4; i++) {
        __nv_bfloat16 h = __float2bfloat16(a[i]);
        float r = a[i] - __bfloat162float(h);
        __nv_bfloat16 l = __float2bfloat16(r);
        hs[i] = __bfloat16_as_ushort(h);
        ls[i] = __bfloat16_as_ushort(l);
    }
    hi.x = (uint32_t)hs[0] | ((uint32_t)hs[1] << 16);
    hi.y = (uint32_t)hs[2] | ((uint32_t)hs[3] << 16);
    lo.x = (uint32_t)ls[0] | ((uint32_t)ls[1] << 16);
    lo.y = (uint32_t)ls[2] | ((uint32_t)ls[3] << 16);
}

// ------------------------- K3: new_W = W - P u^T, split to bf16 hi/lo -------------------------
__global__ void k_wsplit(const float* __restrict__ w) {
    int n = blockIdx.x;
    int tid = threadIdx.x;
    __shared__ float sP[8];
    if (tid < 8) sP[tid] = g_P[n * 8 + tid];
    __syncthreads();

    const float4* wr = (const float4*)(w + (size_t)n * DIN);
    uint2* wh = (uint2*)g_wh + (size_t)n * (DIN / 4);
    uint2* wl = (uint2*)g_wl + (size_t)n * (DIN / 4);

    for (int c4 = tid; c4 < DIN / 4; c4 += 256) {
        float4 wv = wr[c4];
        float cx = 0.f, cy = 0.f, cz = 0.f, cw = 0.f;
#pragma unroll
        for (int j = 0; j < 8; j++) {
            float4 u4 = *(const float4*)(g_un + j * DIN + c4 * 4);
            float pj = sP[j];
            cx += pj * u4.x; cy += pj * u4.y; cz += pj * u4.z; cw += pj * u4.w;
        }
        uint2 hi, lo;
        split4(wv.x - cx, wv.y - cy, wv.z - cz, wv.w - cw, hi, lo);
        wh[c4] = hi;
        wl[c4] = lo;
    }
}

// ------------------------- K4: split x to bf16 hi/lo -------------------------
__global__ void k_xsplit(const float* __restrict__ x) {
    size_t idx = (size_t)blockIdx.x * blockDim.x + threadIdx.x;
    size_t stride = (size_t)gridDim.x * blockDim.x;
    const float4* x4 = (const float4*)x;
    uint2* xh = (uint2*)g_xh;
    uint2* xl = (uint2*)g_xl;
    const size_t n4 = (size_t)MTOT * DIN / 4;
    for (size_t i = idx; i < n4; i += stride) {
        float4 v = x4[i];
        uint2 hi, lo;
        split4(v.x, v.y, v.z, v.w, hi, lo);
        xh[i] = hi;
        xl[i] = lo;
    }
}

// ------------------------- K5: main GEMM via mma.sync (HMMA) -------------------------
// out[8192,4096] = Xsplit @ Wsplit^T, 3-term bf16 split, fp32 accumulate.
// CTA tile 128x128, K chunk 32, 4-stage cp.async pipeline, 8 warps (64x32 each).
#define BK 32
#define NCHUNK (DIN / BK)              // 128
#define ARR_BYTES 8192                 // 128 rows x 32 bf16
#define STAGE_BYTES (4 * ARR_BYTES)    // Ah, Al, Bh, Bl
#define NSTAGE 4
#define GEMM_SMEM (NSTAGE * STAGE_BYTES)   // 131072

// SMEM layout per array: row-major 128 rows x 64B, 16B segments XOR-swizzled:
// phys(row, seg) = row*64 + ((seg ^ ((row>>1)&3)) << 4)
__device__ __forceinline__ uint32_t swz(uint32_t row, uint32_t seg) {
    return row * 64u + (((seg ^ ((row >> 1) & 3u)) & 3u) << 4);
}

__device__ __forceinline__ void load_chunk(int c, int st, int m0, int n0,
                                           uint32_t sb, int tid) {
    const int k0 = c * BK;
    uint32_t base = sb + st * STAGE_BYTES;
    const __nv_bfloat16* srcs[4] = {g_xh, g_xl, g_wh, g_wl};
    const int r0s[4] = {m0, m0, n0, n0};
#pragma unroll
    for (int p = 0; p < 4; p++) {
        const __nv_bfloat16* src = srcs[p];
        const int r0 = r0s[p];
        const uint32_t sp = base + p * ARR_BYTES;
#pragma unroll
        for (int it = 0; it < 2; ++it) {
            int idx = tid + it * 256;
            uint32_t row = (uint32_t)(idx >> 2);
            uint32_t seg = (uint32_t)(idx & 3);
            const void* g = src + (size_t)(r0 + (int)row) * DIN + k0 + (int)seg * 8;
            cp_async16(sp + swz(row, seg), g);
        }
    }
}

__global__ void __launch_bounds__(256, 1) k_gemm(float* __restrict__ out) {
    extern __shared__ char smem[];
    uint32_t sb = smem_u32(smem);
    const int tid = threadIdx.x;
    const int wid = tid >> 5;
    const int lane = tid & 31;

    // 64x32 CTA grid of tiles: swizzle bid for a bit of L2 locality
    const int tn = blockIdx.x & 31;
    const int tm = blockIdx.x >> 5;
    const int m0 = tm << 7;
    const int n0 = tn << 7;

    const int warp_m = wid & 1;        // 2 warps over M (64 rows each)
    const int warp_n = wid >> 1;       // 4 warps over N (32 cols each)

    // ldmatrix lane-address components (row within the 128-row array)
    const uint32_t lr  = (uint32_t)(lane & 7);
    const uint32_t q8  = (uint32_t)((lane >> 3) & 1);   // +8 rows
    const uint32_t sk  = (uint32_t)((lane >> 4) & 1);   // k-half (16B seg)

    // Per-lane precomputed row terms for A (4 m16 tiles) and B (2 n16 groups)
    uint32_t a_rt[4], a_sw[4], b_rt[2], b_sw[2];
#pragma unroll
    for (int i = 0; i < 4; i++) {
        uint32_t row = (uint32_t)(warp_m * 64 + i * 16) + lr + q8 * 8;
        a_rt[i] = row * 64u;
        a_sw[i] = (row >> 1) & 3u;
    }
#pragma unroll
    for (int j = 0; j < 2; j++) {
        uint32_t row = (uint32_t)(warp_n * 32 + j * 16) + lr + q8 * 8;
        b_rt[j] = row * 64u;
        b_sw[j] = (row >> 1) & 3u;
    }

    float acc[4][4][4];
#pragma unroll
    for (int i = 0; i < 4; i++)
#pragma unroll
        for (int j = 0; j < 4; j++)
#pragma unroll
            for (int r = 0; r < 4; r++) acc[i][j][r] = 0.f;

    // prologue: fill 3 stages
    load_chunk(0, 0, m0, n0, sb, tid); CP_COMMIT();
    load_chunk(1, 1, m0, n0, sb, tid); CP_COMMIT();
    load_chunk(2, 2, m0, n0, sb, tid); CP_COMMIT();

    for (int c = 0; c < NCHUNK; ++c) {
        const int st = c & 3;
        CP_WAIT2();
        __syncthreads();

        const uint32_t sAh = sb + st * STAGE_BYTES;
        const uint32_t sAl = sAh + ARR_BYTES;
        const uint32_t sBh = sAh + 2 * ARR_BYTES;
        const uint32_t sBl = sAh + 3 * ARR_BYTES;

#pragma unroll
        for (int s = 0; s < 2; ++s) {
            const uint32_t seg = 2u * (uint32_t)s + sk;

            uint32_t ah[4][4], al[4][4], bh[4][2], bl[4][2];
#pragma unroll
            for (int i = 0; i < 4; i++) {
                uint32_t off = a_rt[i] + (((seg ^ a_sw[i]) & 3u) << 4);
                LDMATRIX_X4(ah[i][0], ah[i][1], ah[i][2], ah[i][3], sAh + off);
                LDMATRIX_X4(al[i][0], al[i][1], al[i][2], al[i][3], sAl + off);
            }
#pragma unroll
            for (int j = 0; j < 2; j++) {
                uint32_t off = b_rt[j] + (((seg ^ b_sw[j]) & 3u) << 4);
                uint32_t r0, r1, r2, r3;
                LDMATRIX_X4(r0, r1, r2, r3, sBh + off);
                bh[2 * j][0] = r0; bh[2 * j][1] = r2;
                bh[2 * j + 1][0] = r1; bh[2 * j + 1][1] = r3;
                LDMATRIX_X4(r0, r1, r2, r3, sBl + off);
                bl[2 * j][0] = r0; bl[2 * j][1] = r2;
                bl[2 * j + 1][0] = r1; bl[2 * j + 1][1] = r3;
            }

#pragma unroll
            for (int i = 0; i < 4; i++) {
#pragma unroll
                for (int j = 0; j < 4; j++) {
                    MMA16816(acc[i][j][0], acc[i][j][1], acc[i][j][2], acc[i][j][3],
                             ah[i][0], ah[i][1], ah[i][2], ah[i][3],
                             bh[j][0], bh[j][1]);
                    MMA16816(acc[i][j][0], acc[i][j][1], acc[i][j][2], acc[i][j][3],
                             ah[i][0], ah[i][1], ah[i][2], ah[i][3],
                             bl[j][0], bl[j][1]);
                    MMA16816(acc[i][j][0], acc[i][j][1], acc[i][j][2], acc[i][j][3],
                             al[i][0], al[i][1], al[i][2], al[i][3],
                             bh[j][0], bh[j][1]);
                }
            }
        }

        if (c + 3 < NCHUNK) load_chunk(c + 3, (c + 3) & 3, m0, n0, sb, tid);
        CP_COMMIT();   // uniform group counting (empty groups near the tail)
    }

    // epilogue: direct fp32 stores (thread owns rows m, m+8; cols 2*(lane&3)+{0,1})
    const int rbase = m0 + warp_m * 64 + (lane >> 2);
    const int cbase = n0 + warp_n * 32 + (lane & 3) * 2;
#pragma unroll
    for (int i = 0; i < 4; i++) {
#pragma unroll
        for (int j = 0; j < 4; j++) {
            float2 v0 = make_float2(acc[i][j][0], acc[i][j][1]);
            float2 v1 = make_float2(acc[i][j][2], acc[i][j][3]);
            size_t r0 = (size_t)(rbase + i * 16) * DOUT + (cbase + j * 8);
            size_t r1 = r0 + 8 * (size_t)DOUT;
            *(float2*)(out + r0) = v0;
            *(float2*)(out + r1) = v1;
        }
    }
}

// ------------------------- launch -------------------------
extern "C" void kernel_launch(void* const* d_in, const int* in_sizes, int n_in,
                              void* d_out, int out_size) {
    (void)in_sizes; (void)n_in; (void)out_size;
    const float* x   = (const float*)d_in[0];
    const float* w   = (const float*)d_in[1];
    const float* hra = (const float*)d_in[2];
    float* out = (float*)d_out;

    k_prep<<<1, 256>>>(hra);
    k_wu<<<DOUT, 256>>>(w);
    k_wsplit<<<DOUT, 256>>>(w);
    k_xsplit<<<8192, 256>>>(x);

    cudaFuncSetAttribute(k_gemm, cudaFuncAttributeMaxDynamicSharedMemorySize, GEMM_SMEM);
    k_gemm<<<(MTOT / 128) * (DOUT / 128), 256, GEMM_SMEM>>>(out);
}

// round 3
// speedup vs baseline: 1.1478x; 1.1478x over previous
#include <cuda_runtime.h>
#include <cuda_bf16.h>
#include <cstdint>
#include <cstddef>

#define DIN  4096
#define DOUT 4096
#define RNK  8
#define MTOT 8192            // 4*2048 rows of x

// ------------------------- scratch (__device__ globals) -------------------------
__device__ float g_un[RNK * DIN];          // normalized Householder vectors, [r][DIN]
__device__ float g_T[RNK * RNK];           // compact-WY T (8x8)
__device__ float g_P[DOUT * RNK];          // P = (W U) T, [DOUT][8]
__device__ __nv_bfloat16 g_wh[(size_t)DOUT * DIN];
__device__ __nv_bfloat16 g_wl[(size_t)DOUT * DIN];
__device__ __nv_bfloat16 g_xh[(size_t)MTOT * DIN];
__device__ __nv_bfloat16 g_xl[(size_t)MTOT * DIN];

// ------------------------- PTX helpers (family-safe: sm_80-era) -------------------------
__device__ __forceinline__ uint32_t smem_u32(const void* p) {
    uint32_t a;
    asm("{ .reg .u64 t; cvta.to.shared.u64 t, %1; cvt.u32.u64 %0, t; }" : "=r"(a) : "l"(p));
    return a;
}

__device__ __forceinline__ void cp_async16(uint32_t saddr, const void* gptr) {
    asm volatile("cp.async.cg.shared.global [%0], [%1], 16;" :: "r"(saddr), "l"(gptr));
}
#define CP_COMMIT() asm volatile("cp.async.commit_group;" ::: "memory")
#define CP_WAIT1()  asm volatile("cp.async.wait_group 1;" ::: "memory")

#define LDMATRIX_X4(r0, r1, r2, r3, addr) \
    asm volatile("ldmatrix.sync.aligned.m8n8.x4.shared.b16 {%0,%1,%2,%3}, [%4];" \
                 : "=r"(r0), "=r"(r1), "=r"(r2), "=r"(r3) : "r"(addr))

#define MMA16816(d0, d1, d2, d3, a0, a1, a2, a3, b0, b1) \
    asm volatile("mma.sync.aligned.m16n8k16.row.col.f32.bf16.bf16.f32 " \
                 "{%0,%1,%2,%3}, {%4,%5,%6,%7}, {%8,%9}, {%0,%1,%2,%3};" \
                 : "+f"(d0), "+f"(d1), "+f"(d2), "+f"(d3) \
                 : "r"(a0), "r"(a1), "r"(a2), "r"(a3), "r"(b0), "r"(b1))

// ------------------------- K1: normalize u, Gram, build T -------------------------
__global__ void k_prep(const float* __restrict__ hra) {
    __shared__ float sR[64];
    __shared__ float sInv[8];
    int tid = threadIdx.x;
    if (tid < 64) sR[tid] = 0.f;
    __syncthreads();

    float acc[8][8];
#pragma unroll
    for (int i = 0; i < 8; i++)
#pragma unroll
        for (int j = 0; j < 8; j++) acc[i][j] = 0.f;

    for (int k = tid; k < DIN; k += 256) {
        float v[8];
#pragma unroll
        for (int i = 0; i < 8; i++) v[i] = hra[k * 8 + i];
#pragma unroll
        for (int i = 0; i < 8; i++)
#pragma unroll
            for (int j = 0; j < 8; j++) acc[i][j] += v[i] * v[j];
    }
#pragma unroll
    for (int i = 0; i < 8; i++)
#pragma unroll
        for (int j = 0; j < 8; j++) atomicAdd(&sR[i * 8 + j], acc[i][j]);
    __syncthreads();

    if (tid < 8) sInv[tid] = 1.0f / sqrtf(sR[tid * 8 + tid]);
    __syncthreads();

    for (int k = tid; k < DIN; k += 256) {
#pragma unroll
        for (int i = 0; i < 8; i++) g_un[i * DIN + k] = hra[k * 8 + i] * sInv[i];
    }

    if (tid == 0) {
        float G[8][8], T[8][8];
        for (int i = 0; i < 8; i++)
            for (int j = 0; j < 8; j++) G[i][j] = sR[i * 8 + j] * sInv[i] * sInv[j];
        for (int i = 0; i < 8; i++)
            for (int j = 0; j < 8; j++) T[i][j] = (i == j) ? 2.f : 0.f;
        for (int j = 1; j < 8; j++)
            for (int i = 0; i < j; i++) {
                float s = 0.f;
                for (int l = i; l < j; l++) s += T[i][l] * G[l][j];
                T[i][j] = -2.f * s;
            }
        for (int i = 0; i < 8; i++)
            for (int j = 0; j < 8; j++) g_T[i * 8 + j] = T[i][j];
    }
}

// ------------------------- K2: P = (W U) T  (one block per W row) -------------------------
__global__ void k_wu(const float* __restrict__ w) {
    int n = blockIdx.x;
    int tid = threadIdx.x;
    __shared__ float sAcc[8];
    if (tid < 8) sAcc[tid] = 0.f;
    __syncthreads();

    float part[8] = {0, 0, 0, 0, 0, 0, 0, 0};
    const float* wr = w + (size_t)n * DIN;
    for (int c = tid; c < DIN; c += 256) {
        float wv = wr[c];
#pragma unroll
        for (int i = 0; i < 8; i++) part[i] += wv * g_un[i * DIN + c];
    }
#pragma unroll
    for (int i = 0; i < 8; i++) {
        float v = part[i];
        v += __shfl_down_sync(0xFFFFFFFFu, v, 16);
        v += __shfl_down_sync(0xFFFFFFFFu, v, 8);
        v += __shfl_down_sync(0xFFFFFFFFu, v, 4);
        v += __shfl_down_sync(0xFFFFFFFFu, v, 2);
        v += __shfl_down_sync(0xFFFFFFFFu, v, 1);
        if ((tid & 31) == 0) atomicAdd(&sAcc[i], v);
    }
    __syncthreads();
    if (tid < 8) {
        int j = tid;
        float p = 0.f;
#pragma unroll
        for (int i = 0; i < 8; i++) p += sAcc[i] * g_T[i * 8 + j];
        g_P[n * 8 + j] = p;
    }
}

// ------------------------- split helper -------------------------
__device__ __forceinline__ void split4(float a0, float a1, float a2, float a3,
                                       uint2& hi, uint2& lo) {
    unsigned short hs[4], ls[4];
    float a[4] = {a0, a1, a2, a3};
#pragma unroll
    for (int i = 0; i < 4; i++) {
        __nv_bfloat16 h = __float2bfloat16(a[i]);
        float r = a[i] - __bfloat162float(h);
        __nv_bfloat16 l = __float2bfloat16(r);
        hs[i] = __bfloat16_as_ushort(h);
        ls[i] = __bfloat16_as_ushort(l);
    }
    hi.x = (uint32_t)hs[0] | ((uint32_t)hs[1] << 16);
    hi.y = (uint32_t)hs[2] | ((uint32_t)hs[3] << 16);
    lo.x = (uint32_t)ls[0] | ((uint32_t)ls[1] << 16);
    lo.y = (uint32_t)ls[2] | ((uint32_t)ls[3] << 16);
}

// ------------------------- K3: new_W = W - P u^T, split to bf16 hi/lo -------------------------
__global__ void k_wsplit(const float* __restrict__ w) {
    int n = blockIdx.x;
    int tid = threadIdx.x;
    __shared__ float sP[8];
    if (tid < 8) sP[tid] = g_P[n * 8 + tid];
    __syncthreads();

    const float4* wr = (const float4*)(w + (size_t)n * DIN);
    uint2* wh = (uint2*)g_wh + (size_t)n * (DIN / 4);
    uint2* wl = (uint2*)g_wl + (size_t)n * (DIN / 4);

    for (int c4 = tid; c4 < DIN / 4; c4 += 256) {
        float4 wv = wr[c4];
        float cx = 0.f, cy = 0.f, cz = 0.f, cw = 0.f;
#pragma unroll
        for (int j = 0; j < 8; j++) {
            float4 u4 = *(const float4*)(g_un + j * DIN + c4 * 4);
            float pj = sP[j];
            cx += pj * u4.x; cy += pj * u4.y; cz += pj * u4.z; cw += pj * u4.w;
        }
        uint2 hi, lo;
        split4(wv.x - cx, wv.y - cy, wv.z - cz, wv.w - cw, hi, lo);
        wh[c4] = hi;
        wl[c4] = lo;
    }
}

// ------------------------- K4: split x to bf16 hi/lo -------------------------
__global__ void k_xsplit(const float* __restrict__ x) {
    size_t idx = (size_t)blockIdx.x * blockDim.x + threadIdx.x;
    size_t stride = (size_t)gridDim.x * blockDim.x;
    const float4* x4 = (const float4*)x;
    uint2* xh = (uint2*)g_xh;
    uint2* xl = (uint2*)g_xl;
    const size_t n4 = (size_t)MTOT * DIN / 4;
    for (size_t i = idx; i < n4; i += stride) {
        float4 v = x4[i];
        uint2 hi, lo;
        split4(v.x, v.y, v.z, v.w, hi, lo);
        xh[i] = hi;
        xl[i] = lo;
    }
}

// ------------------------- K5: main GEMM via mma.sync (HMMA) -------------------------
// out[8192,4096] = Xsplit @ Wsplit^T, 3-term bf16 split, fp32 accumulate.
// CTA tile 128x128, K chunk 64, 3-stage cp.async pipeline, 8 warps (64x32 each).
// Next-chunk loads interleaved with the 4 k16 compute steps.
#define BK 64
#define NCHUNK (DIN / BK)              // 64
#define ARR_BYTES 16384                // 128 rows x 128 B
#define STAGE_BYTES (4 * ARR_BYTES)    // Ah, Al, Bh, Bl = 64 KB
#define NSTAGE 3
#define GEMM_SMEM (NSTAGE * STAGE_BYTES)   // 196608

// SMEM layout per array: 128 rows x 128B; 16B segments XOR-swizzled:
// phys(row, seg) = row*128 + ((seg ^ (row&7)) << 4)
__device__ __forceinline__ uint32_t swz(uint32_t row, uint32_t seg) {
    return row * 128u + (((seg ^ (row & 7u)) & 7u) << 4);
}

// Load one array (quarter) of chunk c into stage st. arrays: 0=xh 1=xl 2=wh 3=wl
__device__ __forceinline__ void load_quarter(int c, int st, int p, int m0, int n0,
                                             uint32_t sb, int tid) {
    const int k0 = c * BK;
    const __nv_bfloat16* src = (p == 0) ? g_xh : (p == 1) ? g_xl : (p == 2) ? g_wh : g_wl;
    const int r0 = (p < 2) ? m0 : n0;
    const uint32_t sp = sb + st * STAGE_BYTES + p * ARR_BYTES;
    const uint32_t seg = (uint32_t)(tid & 7);
    const uint32_t rbase = (uint32_t)(tid >> 3);      // 0..31
#pragma unroll
    for (int i = 0; i < 4; ++i) {
        uint32_t row = rbase + i * 32u;
        const void* g = src + (size_t)(r0 + (int)row) * DIN + k0 + (int)seg * 8;
        cp_async16(sp + swz(row, seg), g);
    }
}

__global__ void __launch_bounds__(256, 1) k_gemm(float* __restrict__ out) {
    extern __shared__ char smem[];
    uint32_t sb = smem_u32(smem);
    const int tid = threadIdx.x;
    const int wid = tid >> 5;
    const int lane = tid & 31;

    const int tn = blockIdx.x & 31;
    const int tm = blockIdx.x >> 5;
    const int m0 = tm << 7;
    const int n0 = tn << 7;

    const int warp_m = wid & 1;        // 2 warps over M (64 rows each)
    const int warp_n = wid >> 1;       // 4 warps over N (32 cols each)

    const uint32_t lr  = (uint32_t)(lane & 7);
    const uint32_t q8  = (uint32_t)((lane >> 3) & 1);   // +8 rows
    const uint32_t sk  = (uint32_t)((lane >> 4) & 1);   // 16B half within k16

    // Per-lane precomputed row terms for A (4 m16 tiles) and B (2 n16 groups)
    uint32_t a_rt[4], a_sw[4], b_rt[2], b_sw[2];
#pragma unroll
    for (int i = 0; i < 4; i++) {
        uint32_t row = (uint32_t)(warp_m * 64 + i * 16) + lr + q8 * 8;
        a_rt[i] = row * 128u;
        a_sw[i] = row & 7u;
    }
#pragma unroll
    for (int j = 0; j < 2; j++) {
        uint32_t row = (uint32_t)(warp_n * 32 + j * 16) + lr + q8 * 8;
        b_rt[j] = row * 128u;
        b_sw[j] = row & 7u;
    }

    float acc[4][4][4];
#pragma unroll
    for (int i = 0; i < 4; i++)
#pragma unroll
        for (int j = 0; j < 4; j++)
#pragma unroll
            for (int r = 0; r < 4; r++) acc[i][j][r] = 0.f;

    // prologue: fill 2 stages
#pragma unroll
    for (int p = 0; p < 4; p++) load_quarter(0, 0, p, m0, n0, sb, tid);
    CP_COMMIT();
#pragma unroll
    for (int p = 0; p < 4; p++) load_quarter(1, 1, p, m0, n0, sb, tid);
    CP_COMMIT();

    for (int c = 0; c < NCHUNK; ++c) {
        const int st = c % 3;
        const int pf = c + 2;                 // chunk to prefetch
        const int pst = pf % 3;
        const bool do_pf = (pf < NCHUNK);

        CP_WAIT1();
        __syncthreads();

        const uint32_t sAh = sb + st * STAGE_BYTES;
        const uint32_t sAl = sAh + ARR_BYTES;
        const uint32_t sBh = sAh + 2 * ARR_BYTES;
        const uint32_t sBl = sAh + 3 * ARR_BYTES;

#pragma unroll
        for (int s = 0; s < 4; ++s) {
            const uint32_t seg = 2u * (uint32_t)s + sk;

            uint32_t ah[4][4], al[4][4], bh[4][2], bl[4][2];
#pragma unroll
            for (int i = 0; i < 4; i++) {
                uint32_t off = a_rt[i] + (((seg ^ a_sw[i]) & 7u) << 4);
                LDMATRIX_X4(ah[i][0], ah[i][1], ah[i][2], ah[i][3], sAh + off);
                LDMATRIX_X4(al[i][0], al[i][1], al[i][2], al[i][3], sAl + off);
            }
#pragma unroll
            for (int j = 0; j < 2; j++) {
                uint32_t off = b_rt[j] + (((seg ^ b_sw[j]) & 7u) << 4);
                uint32_t r0, r1, r2, r3;
                LDMATRIX_X4(r0, r1, r2, r3, sBh + off);
                bh[2 * j][0] = r0; bh[2 * j][1] = r2;
                bh[2 * j + 1][0] = r1; bh[2 * j + 1][1] = r3;
                LDMATRIX_X4(r0, r1, r2, r3, sBl + off);
                bl[2 * j][0] = r0; bl[2 * j][1] = r2;
                bl[2 * j + 1][0] = r1; bl[2 * j + 1][1] = r3;
            }

            // interleave one quarter of the prefetch chunk's loads per k16 step
            if (do_pf) load_quarter(pf, pst, s, m0, n0, sb, tid);

#pragma unroll
            for (int i = 0; i < 4; i++) {
#pragma unroll
                for (int j = 0; j < 4; j++) {
                    MMA16816(acc[i][j][0], acc[i][j][1], acc[i][j][2], acc[i][j][3],
                             ah[i][0], ah[i][1], ah[i][2], ah[i][3],
                             bh[j][0], bh[j][1]);
                    MMA16816(acc[i][j][0], acc[i][j][1], acc[i][j][2], acc[i][j][3],
                             ah[i][0], ah[i][1], ah[i][2], ah[i][3],
                             bl[j][0], bl[j][1]);
                    MMA16816(acc[i][j][0], acc[i][j][1], acc[i][j][2], acc[i][j][3],
                             al[i][0], al[i][1], al[i][2], al[i][3],
                             bh[j][0], bh[j][1]);
                }
            }
        }
        CP_COMMIT();   // one group per chunk (possibly empty near the tail)
    }

    // epilogue: direct fp32 stores (thread owns rows m, m+8; cols 2*(lane&3)+{0,1})
    const int rbase = m0 + warp_m * 64 + (lane >> 2);
    const int cbase = n0 + warp_n * 32 + (lane & 3) * 2;
#pragma unroll
    for (int i = 0; i < 4; i++) {
#pragma unroll
        for (int j = 0; j < 4; j++) {
            float2 v0 = make_float2(acc[i][j][0], acc[i][j][1]);
            float2 v1 = make_float2(acc[i][j][2], acc[i][j][3]);
            size_t r0 = (size_t)(rbase + i * 16) * DOUT + (cbase + j * 8);
            size_t r1 = r0 + 8 * (size_t)DOUT;
            *(float2*)(out + r0) = v0;
            *(float2*)(out + r1) = v1;
        }
    }
}

// ------------------------- launch -------------------------
extern "C" void kernel_launch(void* const* d_in, const int* in_sizes, int n_in,
                              void* d_out, int out_size) {
    (void)in_sizes; (void)n_in; (void)out_size;
    const float* x   = (const float*)d_in[0];
    const float* w   = (const float*)d_in[1];
    const float* hra = (const float*)d_in[2];
    float* out = (float*)d_out;

    k_prep<<<1, 256>>>(hra);
    k_wu<<<DOUT, 256>>>(w);
    k_wsplit<<<DOUT, 256>>>(w);
    k_xsplit<<<8192, 256>>>(x);

    cudaFuncSetAttribute(k_gemm, cudaFuncAttributeMaxDynamicSharedMemorySize, GEMM_SMEM);
    k_gemm<<<(MTOT / 128) * (DOUT / 128), 256, GEMM_SMEM>>>(out);
}

// round 4
// speedup vs baseline: 2.6834x; 2.3379x over previous
#include <cuda_runtime.h>
#include <cuda_bf16.h>
#include <cuda_fp16.h>
#include <cstdint>
#include <cstddef>

#define DIN  4096
#define DOUT 4096
#define RNK  8
#define MTOT 8192            // 4*2048 rows of x

// ------------------------- scratch (__device__ globals) -------------------------
__device__ float g_un[RNK * DIN];          // normalized Householder vectors, [r][DIN]
__device__ float g_T[RNK * RNK];           // compact-WY T (8x8)
__device__ float g_P[DOUT * RNK];          // P = (W U) T, [DOUT][8]
__device__ __half g_wf[(size_t)DOUT * DIN];   // fp16 new W
__device__ __half g_xf[(size_t)MTOT * DIN];   // fp16 x

// ------------------------- PTX helpers (family-safe: sm_80-era) -------------------------
__device__ __forceinline__ uint32_t smem_u32(const void* p) {
    uint32_t a;
    asm("{ .reg .u64 t; cvta.to.shared.u64 t, %1; cvt.u32.u64 %0, t; }" : "=r"(a) : "l"(p));
    return a;
}

__device__ __forceinline__ void cp_async16(uint32_t saddr, const void* gptr) {
    asm volatile("cp.async.cg.shared.global [%0], [%1], 16;" :: "r"(saddr), "l"(gptr));
}
#define CP_COMMIT() asm volatile("cp.async.commit_group;" ::: "memory")
#define CP_WAIT2()  asm volatile("cp.async.wait_group 2;" ::: "memory")

#define LDMATRIX_X4(r0, r1, r2, r3, addr) \
    asm volatile("ldmatrix.sync.aligned.m8n8.x4.shared.b16 {%0,%1,%2,%3}, [%4];" \
                 : "=r"(r0), "=r"(r1), "=r"(r2), "=r"(r3) : "r"(addr))

#define MMA16816F16(d0, d1, d2, d3, a0, a1, a2, a3, b0, b1) \
    asm volatile("mma.sync.aligned.m16n8k16.row.col.f32.f16.f16.f32 " \
                 "{%0,%1,%2,%3}, {%4,%5,%6,%7}, {%8,%9}, {%0,%1,%2,%3};" \
                 : "+f"(d0), "+f"(d1), "+f"(d2), "+f"(d3) \
                 : "r"(a0), "r"(a1), "r"(a2), "r"(a3), "r"(b0), "r"(b1))

// ------------------------- K1: normalize u, Gram, build T -------------------------
__global__ void k_prep(const float* __restrict__ hra) {
    __shared__ float sR[64];
    __shared__ float sInv[8];
    int tid = threadIdx.x;
    if (tid < 64) sR[tid] = 0.f;
    __syncthreads();

    float acc[8][8];
#pragma unroll
    for (int i = 0; i < 8; i++)
#pragma unroll
        for (int j = 0; j < 8; j++) acc[i][j] = 0.f;

    for (int k = tid; k < DIN; k += 256) {
        float v[8];
#pragma unroll
        for (int i = 0; i < 8; i++) v[i] = hra[k * 8 + i];
#pragma unroll
        for (int i = 0; i < 8; i++)
#pragma unroll
            for (int j = 0; j < 8; j++) acc[i][j] += v[i] * v[j];
    }
#pragma unroll
    for (int i = 0; i < 8; i++)
#pragma unroll
        for (int j = 0; j < 8; j++) atomicAdd(&sR[i * 8 + j], acc[i][j]);
    __syncthreads();

    if (tid < 8) sInv[tid] = 1.0f / sqrtf(sR[tid * 8 + tid]);
    __syncthreads();

    for (int k = tid; k < DIN; k += 256) {
#pragma unroll
        for (int i = 0; i < 8; i++) g_un[i * DIN + k] = hra[k * 8 + i] * sInv[i];
    }

    if (tid == 0) {
        float G[8][8], T[8][8];
        for (int i = 0; i < 8; i++)
            for (int j = 0; j < 8; j++) G[i][j] = sR[i * 8 + j] * sInv[i] * sInv[j];
        for (int i = 0; i < 8; i++)
            for (int j = 0; j < 8; j++) T[i][j] = (i == j) ? 2.f : 0.f;
        for (int j = 1; j < 8; j++)
            for (int i = 0; i < j; i++) {
                float s = 0.f;
                for (int l = i; l < j; l++) s += T[i][l] * G[l][j];
                T[i][j] = -2.f * s;
            }
        for (int i = 0; i < 8; i++)
            for (int j = 0; j < 8; j++) g_T[i * 8 + j] = T[i][j];
    }
}

// ------------------------- K2: P = (W U) T  (one block per W row) -------------------------
__global__ void k_wu(const float* __restrict__ w) {
    int n = blockIdx.x;
    int tid = threadIdx.x;
    __shared__ float sAcc[8];
    if (tid < 8) sAcc[tid] = 0.f;
    __syncthreads();

    float part[8] = {0, 0, 0, 0, 0, 0, 0, 0};
    const float* wr = w + (size_t)n * DIN;
    for (int c = tid; c < DIN; c += 256) {
        float wv = wr[c];
#pragma unroll
        for (int i = 0; i < 8; i++) part[i] += wv * g_un[i * DIN + c];
    }
#pragma unroll
    for (int i = 0; i < 8; i++) {
        float v = part[i];
        v += __shfl_down_sync(0xFFFFFFFFu, v, 16);
        v += __shfl_down_sync(0xFFFFFFFFu, v, 8);
        v += __shfl_down_sync(0xFFFFFFFFu, v, 4);
        v += __shfl_down_sync(0xFFFFFFFFu, v, 2);
        v += __shfl_down_sync(0xFFFFFFFFu, v, 1);
        if ((tid & 31) == 0) atomicAdd(&sAcc[i], v);
    }
    __syncthreads();
    if (tid < 8) {
        int j = tid;
        float p = 0.f;
#pragma unroll
        for (int i = 0; i < 8; i++) p += sAcc[i] * g_T[i * 8 + j];
        g_P[n * 8 + j] = p;
    }
}

// ------------------------- K3: new_W = W - P u^T, convert to fp16 -------------------------
__global__ void k_wconv(const float* __restrict__ w) {
    int n = blockIdx.x;
    int tid = threadIdx.x;
    __shared__ float sP[8];
    if (tid < 8) sP[tid] = g_P[n * 8 + tid];
    __syncthreads();

    const float4* wr = (const float4*)(w + (size_t)n * DIN);
    uint2* wo = (uint2*)g_wf + (size_t)n * (DIN / 4);

    for (int c4 = tid; c4 < DIN / 4; c4 += 256) {
        float4 wv = wr[c4];
        float cx = 0.f, cy = 0.f, cz = 0.f, cw = 0.f;
#pragma unroll
        for (int j = 0; j < 8; j++) {
            float4 u4 = *(const float4*)(g_un + j * DIN + c4 * 4);
            float pj = sP[j];
            cx += pj * u4.x; cy += pj * u4.y; cz += pj * u4.z; cw += pj * u4.w;
        }
        __half2 h0 = __floats2half2_rn(wv.x - cx, wv.y - cy);
        __half2 h1 = __floats2half2_rn(wv.z - cz, wv.w - cw);
        uint2 o;
        o.x = *(uint32_t*)&h0;
        o.y = *(uint32_t*)&h1;
        wo[c4] = o;
    }
}

// ------------------------- K4: convert x to fp16 -------------------------
__global__ void k_xconv(const float* __restrict__ x) {
    size_t idx = (size_t)blockIdx.x * blockDim.x + threadIdx.x;
    size_t stride = (size_t)gridDim.x * blockDim.x;
    const float4* x4 = (const float4*)x;
    uint2* xo = (uint2*)g_xf;
    const size_t n4 = (size_t)MTOT * DIN / 4;
    for (size_t i = idx; i < n4; i += stride) {
        float4 v = x4[i];
        __half2 h0 = __floats2half2_rn(v.x, v.y);
        __half2 h1 = __floats2half2_rn(v.z, v.w);
        uint2 o;
        o.x = *(uint32_t*)&h0;
        o.y = *(uint32_t*)&h1;
        xo[i] = o;
    }
}

// ------------------------- K5: main GEMM via mma.sync fp16 (single pass) -------------------------
// out[8192,4096] = Xf @ Wf^T, fp32 accumulate.
// CTA tile 128x128, K chunk 64, 4-stage cp.async pipeline, 8 warps (64x32 each).
#define BK 64
#define NCHUNK (DIN / BK)              // 64
#define ARR_BYTES 16384                // 128 rows x 128 B
#define STAGE_BYTES (2 * ARR_BYTES)    // A, B = 32 KB
#define NSTAGE 4
#define GEMM_SMEM (NSTAGE * STAGE_BYTES)   // 131072

// SMEM layout per array: 128 rows x 128B; 16B segments XOR-swizzled:
// phys(row, seg) = row*128 + ((seg ^ (row&7)) << 4)
__device__ __forceinline__ uint32_t swz(uint32_t row, uint32_t seg) {
    return row * 128u + (((seg ^ (row & 7u)) & 7u) << 4);
}

// Load one array (half) of chunk c into stage st. p: 0=x 1=w
__device__ __forceinline__ void load_half(int c, int st, int p, int m0, int n0,
                                          uint32_t sb, int tid) {
    const int k0 = c * BK;
    const __half* src = (p == 0) ? g_xf : g_wf;
    const int r0 = (p == 0) ? m0 : n0;
    const uint32_t sp = sb + st * STAGE_BYTES + p * ARR_BYTES;
    const uint32_t seg = (uint32_t)(tid & 7);
    const uint32_t rbase = (uint32_t)(tid >> 3);      // 0..31
#pragma unroll
    for (int i = 0; i < 4; ++i) {
        uint32_t row = rbase + i * 32u;
        const void* g = src + (size_t)(r0 + (int)row) * DIN + k0 + (int)seg * 8;
        cp_async16(sp + swz(row, seg), g);
    }
}

__global__ void __launch_bounds__(256, 1) k_gemm(float* __restrict__ out) {
    extern __shared__ char smem[];
    uint32_t sb = smem_u32(smem);
    const int tid = threadIdx.x;
    const int wid = tid >> 5;
    const int lane = tid & 31;

    const int tn = blockIdx.x & 31;
    const int tm = blockIdx.x >> 5;
    const int m0 = tm << 7;
    const int n0 = tn << 7;

    const int warp_m = wid & 1;        // 2 warps over M (64 rows each)
    const int warp_n = wid >> 1;       // 4 warps over N (32 cols each)

    const uint32_t lr  = (uint32_t)(lane & 7);
    const uint32_t q8  = (uint32_t)((lane >> 3) & 1);   // +8 rows
    const uint32_t sk  = (uint32_t)((lane >> 4) & 1);   // 16B half within k16

    // Per-lane precomputed row terms for A (4 m16 tiles) and B (2 n16 groups)
    uint32_t a_rt[4], a_sw[4], b_rt[2], b_sw[2];
#pragma unroll
    for (int i = 0; i < 4; i++) {
        uint32_t row = (uint32_t)(warp_m * 64 + i * 16) + lr + q8 * 8;
        a_rt[i] = row * 128u;
        a_sw[i] = row & 7u;
    }
#pragma unroll
    for (int j = 0; j < 2; j++) {
        uint32_t row = (uint32_t)(warp_n * 32 + j * 16) + lr + q8 * 8;
        b_rt[j] = row * 128u;
        b_sw[j] = row & 7u;
    }

    float acc[4][4][4];
#pragma unroll
    for (int i = 0; i < 4; i++)
#pragma unroll
        for (int j = 0; j < 4; j++)
#pragma unroll
            for (int r = 0; r < 4; r++) acc[i][j][r] = 0.f;

    // prologue: fill 3 stages
#pragma unroll
    for (int p = 0; p < 2; p++) load_half(0, 0, p, m0, n0, sb, tid);
    CP_COMMIT();
#pragma unroll
    for (int p = 0; p < 2; p++) load_half(1, 1, p, m0, n0, sb, tid);
    CP_COMMIT();
#pragma unroll
    for (int p = 0; p < 2; p++) load_half(2, 2, p, m0, n0, sb, tid);
    CP_COMMIT();

    for (int c = 0; c < NCHUNK; ++c) {
        const int st = c & 3;
        const int pf = c + 3;                 // chunk to prefetch
        const int pst = pf & 3;
        const bool do_pf = (pf < NCHUNK);

        CP_WAIT2();
        __syncthreads();

        const uint32_t sA = sb + st * STAGE_BYTES;
        const uint32_t sB = sA + ARR_BYTES;

#pragma unroll
        for (int s = 0; s < 4; ++s) {
            const uint32_t seg = 2u * (uint32_t)s + sk;

            uint32_t a[4][4], b[4][2];
#pragma unroll
            for (int i = 0; i < 4; i++) {
                uint32_t off = a_rt[i] + (((seg ^ a_sw[i]) & 7u) << 4);
                LDMATRIX_X4(a[i][0], a[i][1], a[i][2], a[i][3], sA + off);
            }
#pragma unroll
            for (int j = 0; j < 2; j++) {
                uint32_t off = b_rt[j] + (((seg ^ b_sw[j]) & 7u) << 4);
                uint32_t r0, r1, r2, r3;
                LDMATRIX_X4(r0, r1, r2, r3, sB + off);
                b[2 * j][0] = r0; b[2 * j][1] = r2;
                b[2 * j + 1][0] = r1; b[2 * j + 1][1] = r3;
            }

            // interleave prefetch loads: x at step 0, w at step 2
            if (do_pf && (s == 0)) load_half(pf, pst, 0, m0, n0, sb, tid);
            if (do_pf && (s == 2)) load_half(pf, pst, 1, m0, n0, sb, tid);

#pragma unroll
            for (int i = 0; i < 4; i++) {
#pragma unroll
                for (int j = 0; j < 4; j++) {
                    MMA16816F16(acc[i][j][0], acc[i][j][1], acc[i][j][2], acc[i][j][3],
                                a[i][0], a[i][1], a[i][2], a[i][3],
                                b[j][0], b[j][1]);
                }
            }
        }
        CP_COMMIT();   // one group per chunk (possibly empty near the tail)
    }

    // epilogue: direct fp32 stores (thread owns rows m, m+8; cols 2*(lane&3)+{0,1})
    const int rbase = m0 + warp_m * 64 + (lane >> 2);
    const int cbase = n0 + warp_n * 32 + (lane & 3) * 2;
#pragma unroll
    for (int i = 0; i < 4; i++) {
#pragma unroll
        for (int j = 0; j < 4; j++) {
            float2 v0 = make_float2(acc[i][j][0], acc[i][j][1]);
            float2 v1 = make_float2(acc[i][j][2], acc[i][j][3]);
            size_t r0 = (size_t)(rbase + i * 16) * DOUT + (cbase + j * 8);
            size_t r1 = r0 + 8 * (size_t)DOUT;
            *(float2*)(out + r0) = v0;
            *(float2*)(out + r1) = v1;
        }
    }
}

// ------------------------- launch -------------------------
extern "C" void kernel_launch(void* const* d_in, const int* in_sizes, int n_in,
                              void* d_out, int out_size) {
    (void)in_sizes; (void)n_in; (void)out_size;
    const float* x   = (const float*)d_in[0];
    const float* w   = (const float*)d_in[1];
    const float* hra = (const float*)d_in[2];
    float* out = (float*)d_out;

    k_prep<<<1, 256>>>(hra);
    k_wu<<<DOUT, 256>>>(w);
    k_wconv<<<DOUT, 256>>>(w);
    k_xconv<<<8192, 256>>>(x);

    cudaFuncSetAttribute(k_gemm, cudaFuncAttributeMaxDynamicSharedMemorySize, GEMM_SMEM);
    k_gemm<<<(MTOT / 128) * (DOUT / 128), 256, GEMM_SMEM>>>(out);
}

// round 5
// speedup vs baseline: 2.8798x; 1.0732x over previous
#include <cuda_runtime.h>
#include <cuda_bf16.h>
#include <cuda_fp16.h>
#include <cstdint>
#include <cstddef>

#define DIN  4096
#define DOUT 4096
#define RNK  8
#define MTOT 8192            // 4*2048 rows of x

// ------------------------- scratch (__device__ globals) -------------------------
__device__ float g_un[RNK * DIN];          // normalized Householder vectors, [r][DIN]
__device__ float g_T[RNK * RNK];           // compact-WY T (8x8)
__device__ float g_P[DOUT * RNK];          // P = (W U) T, [DOUT][8]
__device__ __half g_wf[(size_t)DOUT * DIN];   // fp16 new W
__device__ __half g_xf[(size_t)MTOT * DIN];   // fp16 x

// ------------------------- PTX helpers (family-safe: sm_80-era) -------------------------
__device__ __forceinline__ uint32_t smem_u32(const void* p) {
    uint32_t a;
    asm("{ .reg .u64 t; cvta.to.shared.u64 t, %1; cvt.u32.u64 %0, t; }" : "=r"(a) : "l"(p));
    return a;
}

__device__ __forceinline__ void cp_async16(uint32_t saddr, const void* gptr) {
    asm volatile("cp.async.cg.shared.global [%0], [%1], 16;" :: "r"(saddr), "l"(gptr));
}
#define CP_COMMIT() asm volatile("cp.async.commit_group;" ::: "memory")
#define CP_WAIT2()  asm volatile("cp.async.wait_group 2;" ::: "memory")

#define LDMATRIX_X4(r0, r1, r2, r3, addr) \
    asm volatile("ldmatrix.sync.aligned.m8n8.x4.shared.b16 {%0,%1,%2,%3}, [%4];" \
                 : "=r"(r0), "=r"(r1), "=r"(r2), "=r"(r3) : "r"(addr))

#define MMA16816F16(d0, d1, d2, d3, a0, a1, a2, a3, b0, b1) \
    asm volatile("mma.sync.aligned.m16n8k16.row.col.f32.f16.f16.f32 " \
                 "{%0,%1,%2,%3}, {%4,%5,%6,%7}, {%8,%9}, {%0,%1,%2,%3};" \
                 : "+f"(d0), "+f"(d1), "+f"(d2), "+f"(d3) \
                 : "r"(a0), "r"(a1), "r"(a2), "r"(a3), "r"(b0), "r"(b1))

// ------------------------- K1: normalize u, Gram, build T -------------------------
__global__ void k_prep(const float* __restrict__ hra) {
    __shared__ float sR[64];
    __shared__ float sInv[8];
    int tid = threadIdx.x;
    if (tid < 64) sR[tid] = 0.f;
    __syncthreads();

    float acc[8][8];
#pragma unroll
    for (int i = 0; i < 8; i++)
#pragma unroll
        for (int j = 0; j < 8; j++) acc[i][j] = 0.f;

    for (int k = tid; k < DIN; k += 256) {
        float v[8];
#pragma unroll
        for (int i = 0; i < 8; i++) v[i] = hra[k * 8 + i];
#pragma unroll
        for (int i = 0; i < 8; i++)
#pragma unroll
            for (int j = 0; j < 8; j++) acc[i][j] += v[i] * v[j];
    }
#pragma unroll
    for (int i = 0; i < 8; i++)
#pragma unroll
        for (int j = 0; j < 8; j++) atomicAdd(&sR[i * 8 + j], acc[i][j]);
    __syncthreads();

    if (tid < 8) sInv[tid] = 1.0f / sqrtf(sR[tid * 8 + tid]);
    __syncthreads();

    for (int k = tid; k < DIN; k += 256) {
#pragma unroll
        for (int i = 0; i < 8; i++) g_un[i * DIN + k] = hra[k * 8 + i] * sInv[i];
    }

    if (tid == 0) {
        float G[8][8], T[8][8];
        for (int i = 0; i < 8; i++)
            for (int j = 0; j < 8; j++) G[i][j] = sR[i * 8 + j] * sInv[i] * sInv[j];
        for (int i = 0; i < 8; i++)
            for (int j = 0; j < 8; j++) T[i][j] = (i == j) ? 2.f : 0.f;
        for (int j = 1; j < 8; j++)
            for (int i = 0; i < j; i++) {
                float s = 0.f;
                for (int l = i; l < j; l++) s += T[i][l] * G[l][j];
                T[i][j] = -2.f * s;
            }
        for (int i = 0; i < 8; i++)
            for (int j = 0; j < 8; j++) g_T[i * 8 + j] = T[i][j];
    }
}

// ------------------------- K2: P = (W U) T  (one block per W row) -------------------------
__global__ void k_wu(const float* __restrict__ w) {
    int n = blockIdx.x;
    int tid = threadIdx.x;
    __shared__ float sAcc[8];
    if (tid < 8) sAcc[tid] = 0.f;
    __syncthreads();

    float part[8] = {0, 0, 0, 0, 0, 0, 0, 0};
    const float* wr = w + (size_t)n * DIN;
    for (int c = tid; c < DIN; c += 256) {
        float wv = wr[c];
#pragma unroll
        for (int i = 0; i < 8; i++) part[i] += wv * g_un[i * DIN + c];
    }
#pragma unroll
    for (int i = 0; i < 8; i++) {
        float v = part[i];
        v += __shfl_down_sync(0xFFFFFFFFu, v, 16);
        v += __shfl_down_sync(0xFFFFFFFFu, v, 8);
        v += __shfl_down_sync(0xFFFFFFFFu, v, 4);
        v += __shfl_down_sync(0xFFFFFFFFu, v, 2);
        v += __shfl_down_sync(0xFFFFFFFFu, v, 1);
        if ((tid & 31) == 0) atomicAdd(&sAcc[i], v);
    }
    __syncthreads();
    if (tid < 8) {
        int j = tid;
        float p = 0.f;
#pragma unroll
        for (int i = 0; i < 8; i++) p += sAcc[i] * g_T[i * 8 + j];
        g_P[n * 8 + j] = p;
    }
}

// ------------------------- K3: new_W = W - P u^T, convert to fp16 -------------------------
__global__ void k_wconv(const float* __restrict__ w) {
    int n = blockIdx.x;
    int tid = threadIdx.x;
    __shared__ float sP[8];
    if (tid < 8) sP[tid] = g_P[n * 8 + tid];
    __syncthreads();

    const float4* wr = (const float4*)(w + (size_t)n * DIN);
    uint2* wo = (uint2*)g_wf + (size_t)n * (DIN / 4);

    for (int c4 = tid; c4 < DIN / 4; c4 += 256) {
        float4 wv = wr[c4];
        float cx = 0.f, cy = 0.f, cz = 0.f, cw = 0.f;
#pragma unroll
        for (int j = 0; j < 8; j++) {
            float4 u4 = *(const float4*)(g_un + j * DIN + c4 * 4);
            float pj = sP[j];
            cx += pj * u4.x; cy += pj * u4.y; cz += pj * u4.z; cw += pj * u4.w;
        }
        __half2 h0 = __floats2half2_rn(wv.x - cx, wv.y - cy);
        __half2 h1 = __floats2half2_rn(wv.z - cz, wv.w - cw);
        uint2 o;
        o.x = *(uint32_t*)&h0;
        o.y = *(uint32_t*)&h1;
        wo[c4] = o;
    }
}

// ------------------------- K4: convert x to fp16 -------------------------
__global__ void k_xconv(const float* __restrict__ x) {
    size_t idx = (size_t)blockIdx.x * blockDim.x + threadIdx.x;
    size_t stride = (size_t)gridDim.x * blockDim.x;
    const float4* x4 = (const float4*)x;
    uint2* xo = (uint2*)g_xf;
    const size_t n4 = (size_t)MTOT * DIN / 4;
    for (size_t i = idx; i < n4; i += stride) {
        float4 v = x4[i];
        __half2 h0 = __floats2half2_rn(v.x, v.y);
        __half2 h1 = __floats2half2_rn(v.z, v.w);
        uint2 o;
        o.x = *(uint32_t*)&h0;
        o.y = *(uint32_t*)&h1;
        xo[i] = o;
    }
}

// ------------------------- K5: main GEMM via mma.sync fp16 -------------------------
// out[8192,4096] = Xf @ Wf^T, fp32 accumulate.
// CTA tile 128x256, K chunk 64, 4-stage cp.async pipeline.
// 8 warps: 2 over M x 4 over N; warp tile 64x64 (32 MMAs per k16 step).
#define BK 64
#define NCHUNK (DIN / BK)              // 64
#define A_BYTES 16384                  // 128 rows x 128 B
#define B_BYTES 32768                  // 256 rows x 128 B
#define STAGE_BYTES (A_BYTES + B_BYTES)   // 48 KB
#define NSTAGE 4
#define GEMM_SMEM (NSTAGE * STAGE_BYTES)  // 196608

// SMEM layout per array: rows x 128B; 16B segments XOR-swizzled:
// phys(row, seg) = row*128 + ((seg ^ (row&7)) << 4)
__device__ __forceinline__ uint32_t swz(uint32_t row, uint32_t seg) {
    return row * 128u + (((seg ^ (row & 7u)) & 7u) << 4);
}

// Load 32 rows (one part) of the A array (X) for chunk c into stage st.
__device__ __forceinline__ void load_A_part(int c, int st, int p, int m0,
                                            uint32_t sb, int tid) {
    const uint32_t sp = sb + st * STAGE_BYTES;
    const uint32_t seg = (uint32_t)(tid & 7);
    uint32_t row = (uint32_t)(tid >> 3) + p * 32u;
    const void* g = g_xf + (size_t)(m0 + (int)row) * DIN + c * BK + (int)seg * 8;
    cp_async16(sp + swz(row, seg), g);
}

// Load 32 rows (one part) of the B array (W) for chunk c into stage st.
__device__ __forceinline__ void load_B_part(int c, int st, int p, int n0,
                                            uint32_t sb, int tid) {
    const uint32_t sp = sb + st * STAGE_BYTES + A_BYTES;
    const uint32_t seg = (uint32_t)(tid & 7);
    uint32_t row = (uint32_t)(tid >> 3) + p * 32u;
    const void* g = g_wf + (size_t)(n0 + (int)row) * DIN + c * BK + (int)seg * 8;
    cp_async16(sp + swz(row, seg), g);
}

__device__ __forceinline__ void load_chunk(int c, int st, int m0, int n0,
                                           uint32_t sb, int tid) {
#pragma unroll
    for (int p = 0; p < 4; p++) load_A_part(c, st, p, m0, sb, tid);
#pragma unroll
    for (int p = 0; p < 8; p++) load_B_part(c, st, p, n0, sb, tid);
}

__global__ void __launch_bounds__(256, 1) k_gemm(float* __restrict__ out) {
    extern __shared__ char smem[];
    uint32_t sb = smem_u32(smem);
    const int tid = threadIdx.x;
    const int wid = tid >> 5;
    const int lane = tid & 31;

    // 64 m-tiles x 16 n-tiles
    const int tn = blockIdx.x & 15;
    const int tm = blockIdx.x >> 4;
    const int m0 = tm << 7;
    const int n0 = tn << 8;

    const int warp_m = wid & 1;        // 2 warps over M (64 rows each)
    const int warp_n = wid >> 1;       // 4 warps over N (64 cols each)

    const uint32_t lr  = (uint32_t)(lane & 7);
    const uint32_t q8  = (uint32_t)((lane >> 3) & 1);   // +8 rows
    const uint32_t sk  = (uint32_t)((lane >> 4) & 1);   // 16B half within k16

    // Per-lane precomputed row terms for A (4 m16 tiles) and B (4 n16 groups)
    uint32_t a_rt[4], a_sw[4], b_rt[4], b_sw[4];
#pragma unroll
    for (int i = 0; i < 4; i++) {
        uint32_t row = (uint32_t)(warp_m * 64 + i * 16) + lr + q8 * 8;
        a_rt[i] = row * 128u;
        a_sw[i] = row & 7u;
    }
#pragma unroll
    for (int j = 0; j < 4; j++) {
        uint32_t row = (uint32_t)(warp_n * 64 + j * 16) + lr + q8 * 8;
        b_rt[j] = row * 128u;
        b_sw[j] = row & 7u;
    }

    float acc[4][8][4];
#pragma unroll
    for (int i = 0; i < 4; i++)
#pragma unroll
        for (int j = 0; j < 8; j++)
#pragma unroll
            for (int r = 0; r < 4; r++) acc[i][j][r] = 0.f;

    // prologue: fill 3 stages
    load_chunk(0, 0, m0, n0, sb, tid); CP_COMMIT();
    load_chunk(1, 1, m0, n0, sb, tid); CP_COMMIT();
    load_chunk(2, 2, m0, n0, sb, tid); CP_COMMIT();

    for (int c = 0; c < NCHUNK; ++c) {
        const int st = c & 3;
        const int pf = c + 3;                 // chunk to prefetch
        const int pst = pf & 3;
        const bool do_pf = (pf < NCHUNK);

        CP_WAIT2();
        __syncthreads();

        const uint32_t sA = sb + st * STAGE_BYTES;
        const uint32_t sB = sA + A_BYTES;

#pragma unroll
        for (int s = 0; s < 4; ++s) {
            const uint32_t seg = 2u * (uint32_t)s + sk;

            uint32_t a[4][4], b[8][2];
#pragma unroll
            for (int i = 0; i < 4; i++) {
                uint32_t off = a_rt[i] + (((seg ^ a_sw[i]) & 7u) << 4);
                LDMATRIX_X4(a[i][0], a[i][1], a[i][2], a[i][3], sA + off);
            }
#pragma unroll
            for (int j = 0; j < 4; j++) {
                uint32_t off = b_rt[j] + (((seg ^ b_sw[j]) & 7u) << 4);
                uint32_t r0, r1, r2, r3;
                LDMATRIX_X4(r0, r1, r2, r3, sB + off);
                b[2 * j][0] = r0; b[2 * j][1] = r2;
                b[2 * j + 1][0] = r1; b[2 * j + 1][1] = r3;
            }

            // interleave prefetch loads: spread 12 cp.async over 4 k-steps
            if (do_pf) {
                load_A_part(pf, pst, s, m0, sb, tid);
                load_B_part(pf, pst, 2 * s, n0, sb, tid);
                load_B_part(pf, pst, 2 * s + 1, n0, sb, tid);
            }

#pragma unroll
            for (int i = 0; i < 4; i++) {
#pragma unroll
                for (int j = 0; j < 8; j++) {
                    MMA16816F16(acc[i][j][0], acc[i][j][1], acc[i][j][2], acc[i][j][3],
                                a[i][0], a[i][1], a[i][2], a[i][3],
                                b[j][0], b[j][1]);
                }
            }
        }
        CP_COMMIT();   // one group per chunk (possibly empty near the tail)
    }

    // epilogue: direct fp32 stores (thread owns rows m, m+8; cols 2*(lane&3)+{0,1})
    const int rbase = m0 + warp_m * 64 + (lane >> 2);
    const int cbase = n0 + warp_n * 64 + (lane & 3) * 2;
#pragma unroll
    for (int i = 0; i < 4; i++) {
#pragma unroll
        for (int j = 0; j < 8; j++) {
            float2 v0 = make_float2(acc[i][j][0], acc[i][j][1]);
            float2 v1 = make_float2(acc[i][j][2], acc[i][j][3]);
            size_t r0 = (size_t)(rbase + i * 16) * DOUT + (cbase + j * 8);
            size_t r1 = r0 + 8 * (size_t)DOUT;
            *(float2*)(out + r0) = v0;
            *(float2*)(out + r1) = v1;
        }
    }
}

// ------------------------- launch -------------------------
extern "C" void kernel_launch(void* const* d_in, const int* in_sizes, int n_in,
                              void* d_out, int out_size) {
    (void)in_sizes; (void)n_in; (void)out_size;
    const float* x   = (const float*)d_in[0];
    const float* w   = (const float*)d_in[1];
    const float* hra = (const float*)d_in[2];
    float* out = (float*)d_out;

    k_prep<<<1, 256>>>(hra);
    k_wu<<<DOUT, 256>>>(w);
    k_wconv<<<DOUT, 256>>>(w);
    k_xconv<<<8192, 256>>>(x);

    cudaFuncSetAttribute(k_gemm, cudaFuncAttributeMaxDynamicSharedMemorySize, GEMM_SMEM);
    k_gemm<<<(MTOT / 128) * (DOUT / 256), 256, GEMM_SMEM>>>(out);
}